// round 13
// baseline (speedup 1.0000x reference)
#include <cuda_runtime.h>

// grid [2,160,160,160,3] float32
#define BB 2
#define NX 160
#define NY 160
#define NZ 160

#define TY 12
#define NCHUNK 3                  // z chunks of 60 outputs (2 z-cells per lane)
#define XSPLIT 13
#define XSTEPS 12                 // 156 / 13
#define NTHREADS (TY*32)          // 384
#define NBLOCKS (NCHUNK*13*BB*XSPLIT) // 1014

#define RY (TY + 4)               // 16
#define ZW 64                     // staged z per slice (2 per lane)
#define SLICE (RY * ZW * 3)       // 3072 floats = 12KB
#define ROWW (NZ * 3)             // 480
#define CPR (ZW * 3 / 4)          // 48 16B chunks per staged row
#define Y (ZW * 3)                // 192 floats per y row in slice

__device__ double g_be_sum;
__device__ unsigned int g_be_cnt;

__device__ __forceinline__ void cp16(unsigned int dst_smem, const float* src) {
    asm volatile("cp.async.cg.shared.global [%0], [%1], 16;" :: "r"(dst_smem), "l"(src));
}
__device__ __forceinline__ void cp_commit() {
    asm volatile("cp.async.commit_group;" ::: "memory");
}
__device__ __forceinline__ void cp_wait0() {
    asm volatile("cp.async.wait_group 0;" ::: "memory");
}
__device__ __forceinline__ void cp_wait1() {
    asm volatile("cp.async.wait_group 1;" ::: "memory");
}

#define SHUP(v)  __shfl_up_sync(0xffffffffu, (v), 1)
#define SHDN(v)  __shfl_down_sync(0xffffffffu, (v), 1)

__device__ __forceinline__ float2 lds2(const float* p) {
    return *(const float2*)p;
}

__global__ __launch_bounds__(NTHREADS, 3)
void be_main_kernel(const float* __restrict__ g, float* __restrict__ out) {
    extern __shared__ float ring[];          // 5 * SLICE floats = 60KB (dynamic)
    __shared__ float warp_part[NTHREADS / 32];

    const int tz  = threadIdx.x;             // lane
    const int ty  = threadIdx.y;
    const int tid = ty * 32 + tz;

    const int cz  = blockIdx.x;              // 0..2
    const int cy  = blockIdx.y;              // 0..12
    const int b   = blockIdx.z / XSPLIT;
    const int seg = blockIdx.z % XSPLIT;

    const int zb  = cz * 60;                 // staged window [zb, zb+63]
    const int y0  = 2 + cy * TY;
    const int xs  = 2 + seg * XSTEPS;

    // lane holds cells zA = zb+2*tz, zB = zA+1; both active under one predicate
    const bool active = (tz >= 1) && (tz <= 30) && ((zb + 2 * tz) <= NZ - 4);

    // ---- staging map: 2 chunks/thread; chunk tid+384 is exactly +8 rows ----
    int goffA;
    {
        int row = tid / CPR, col = tid - row * CPR;
        int o = zb * 3 + col * 4;
        if (o > ROWW - 4) o = ROWW - 4;      // clamp: dup lands in cells read only by inactive lanes
        goffA = row * ROWW + o;
    }

    const long long bbase = (long long)b * NX * NY * ROWW + (long long)(y0 - 2) * ROWW;
    const unsigned int ring_s = (unsigned int)__cvta_generic_to_shared(ring);

    auto issue_slice = [&](int gx, int slot) {
        const float* src = g + bbase + (long long)gx * (NY * ROWW);
        unsigned int sb = ring_s + (unsigned int)(slot * SLICE) * 4u + (unsigned int)tid * 16u;
        cp16(sb, src + goffA);
        cp16(sb + NTHREADS * 16u, src + goffA + 8 * ROWW);
    };

    // ---- slot(gx) = (gx - xs + 2) mod 5; prologue xs-2..xs+1 -> slots 0..3 ----
    issue_slice(xs - 2, 0);
    issue_slice(xs - 1, 1);
    issue_slice(xs,     2);
    issue_slice(xs + 1, 3);
    cp_commit();
    cp_wait0();
    __syncthreads();

    const int off0 = (ty + 2) * Y + 6 * tz;

    // delay lines (per cell A/B)
    float c0aA,c0bA,c0cA,c0dA,c0eA, c0aB,c0bB,c0cB,c0dB,c0eB;
    float c1p2A,c1p1A,c1zA, c1p2B,c1p1B,c1zB;
    float c2p2A,c2p1A,c2zA, c2p2B,c2p1B,c2zB;
    float q10A,q11A,q12A, q10B,q11B,q12B;    // q_xy at slice x (all comps)
    float q20A,q21A, q20B,q21B;              // q_xy at slice x-1 (comps 0,1)
    {
        const float* s;
        float2 a, bb, c, u0, u1, u2, l0, l1, l2;
        s = ring + 3 * SLICE;                // xs+1
        a = lds2(s+off0); bb = lds2(s+off0+2); c = lds2(s+off0+4);
        c0aA=a.x; c1p2A=a.y; c2p2A=bb.x; c0aB=bb.y; c1p2B=c.x; c2p2B=c.y;
        s = ring + 2 * SLICE;                // xs
        a = lds2(s+off0); bb = lds2(s+off0+2); c = lds2(s+off0+4);
        c0bA=a.x; c1p1A=a.y; c2p1A=bb.x; c0bB=bb.y; c1p1B=c.x; c2p1B=c.y;
        u0=lds2(s+off0+Y); u1=lds2(s+off0+Y+2); u2=lds2(s+off0+Y+4);
        l0=lds2(s+off0-Y); l1=lds2(s+off0-Y+2); l2=lds2(s+off0-Y+4);
        q10A=u0.x-l0.x; q11A=u0.y-l0.y; q12A=u1.x-l1.x;
        q10B=u1.y-l1.y; q11B=u2.x-l2.x; q12B=u2.y-l2.y;
        s = ring + 1 * SLICE;                // xs-1
        a = lds2(s+off0); bb = lds2(s+off0+2); c = lds2(s+off0+4);
        c0cA=a.x; c1zA=a.y; c2zA=bb.x; c0cB=bb.y; c1zB=c.x; c2zB=c.y;
        u0=lds2(s+off0+Y); u1=lds2(s+off0+Y+2); u2=lds2(s+off0+Y+4);
        l0=lds2(s+off0-Y); l1=lds2(s+off0-Y+2); l2=lds2(s+off0-Y+4);
        q20A=u0.x-l0.x; q21A=u0.y-l0.y;
        q20B=u1.y-l1.y; q21B=u2.x-l2.x;
        s = ring;                            // xs-2 (comp0 centers only)
        a = lds2(s+off0); bb = lds2(s+off0+2);
        c0dA=a.x; c0dB=bb.y;
        c0eA=0.f; c0eB=0.f;
    }
    __syncthreads();            // init reads done before slot 0/4 reuse

    issue_slice(xs + 2, 4); cp_commit();
    issue_slice(xs + 3, 0); cp_commit();

    float acc = 0.0f;
    int gx4 = xs + 4;

    // step x: slots SM1 (x-1, dead: stage x+4), S0 (x), SP1 (x+1), SP2 (x+2 fresh)
    #define DO_STEP(SM1i, S0i, SP1i, SP2i)                                        \
    {                                                                             \
        cp_wait1();                                                               \
        __syncthreads();                                                          \
        {                                                                         \
            int gxs = gx4 > (NX - 1) ? (NX - 1) : gx4;                            \
            issue_slice(gxs, (SM1i)); cp_commit(); ++gx4;                         \
        }                                                                         \
        /* pickup centers of fresh slice x+2 */                                   \
        const float* Sp = ring + (SP2i) * SLICE;                                  \
        float2 n01 = lds2(Sp+off0), n23 = lds2(Sp+off0+2), n45 = lds2(Sp+off0+4); \
        const float c1mA = c1zA, c2mA = c2zA, c1mB = c1zB, c2mB = c2zB;  /* x-1 */\
        c0eA=c0dA; c0dA=c0cA; c0cA=c0bA; c0bA=c0aA; c0aA=n01.x;                   \
        c0eB=c0dB; c0dB=c0cB; c0cB=c0bB; c0bB=c0aB; c0aB=n23.y;                   \
        c1zA=c1p1A; c1p1A=c1p2A; c1p2A=n01.y;                                     \
        c1zB=c1p1B; c1p1B=c1p2B; c1p2B=n45.x;                                     \
        c2zA=c2p1A; c2p1A=c2p2A; c2p2A=n23.x;                                     \
        c2zB=c2p1B; c2p1B=c2p2B; c2p2B=n45.y;                                     \
        /* qn from slice x+1 */                                                   \
        const float* S1 = ring + (SP1i) * SLICE;                                  \
        float2 u0=lds2(S1+off0+Y), u1=lds2(S1+off0+Y+2), u2=lds2(S1+off0+Y+4);    \
        float2 l0=lds2(S1+off0-Y), l1=lds2(S1+off0-Y+2), l2=lds2(S1+off0-Y+4);    \
        const float qn0A=u0.x-l0.x, qn1A=u0.y-l0.y, qn2A=u1.x-l1.x;               \
        const float qn0B=u1.y-l1.y, qn1B=u2.x-l2.x, qn2B=u2.y-l2.y;               \
        /* d = c(x+1) - c(x-1) */                                                 \
        const float d0A=c0bA-c0dA, d1A=c1p1A-c1mA, d2A=c2p1A-c2mA;                \
        const float d0B=c0bB-c0dB, d1B=c1p1B-c1mB, d2B=c2p1B-c2mB;                \
        /* dxz: z+1 of A = B same lane; z-1 of A = B lane-1 */                    \
        const float dxz0A = d0B - SHUP(d0B), dxz0B = SHDN(d0A) - d0A;             \
        const float dxz1A = d1B - SHUP(d1B), dxz1B = SHDN(d1A) - d1A;             \
        const float dxz2A = d2B - SHUP(d2B), dxz2B = SHDN(d2A) - d2A;             \
        /* dyz from q at slice x */                                               \
        const float dyz0A = q10B - SHUP(q10B), dyz0B = SHDN(q10A) - q10A;         \
        const float dyz1A = q11B - SHUP(q11B), dyz1B = SHDN(q11A) - q11A;         \
        const float dyz2A = q12B - SHUP(q12B), dyz2B = SHDN(q12A) - q12A;         \
        /* dzz: z+/-2 = same cell, lanes +/-1 */                                  \
        const float dzz0A = SHUP(c0cA)+SHDN(c0cA)-2.0f*c0cA;                      \
        const float dzz0B = SHUP(c0cB)+SHDN(c0cB)-2.0f*c0cB;                      \
        const float dzz1A = SHUP(c1zA)+SHDN(c1zA)-2.0f*c1zA;                      \
        const float dzz1B = SHUP(c1zB)+SHDN(c1zB)-2.0f*c1zB;                      \
        const float dzz2A = SHUP(c2zA)+SHDN(c2zA)-2.0f*c2zA;                      \
        const float dzz2B = SHUP(c2zB)+SHDN(c2zB)-2.0f*c2zB;                      \
        if (active) {                                                             \
            /* dyy from S0 (slice x), comps 0,1 */                                \
            const float* S0 = ring + (S0i) * SLICE;                               \
            float2 U0=lds2(S0+off0+2*Y), U1=lds2(S0+off0+2*Y+2), U2=lds2(S0+off0+2*Y+4); \
            float2 L0=lds2(S0+off0-2*Y), L1=lds2(S0+off0-2*Y+2), L2=lds2(S0+off0-2*Y+4); \
            {                                                                     \
                const float dxx0 = c0eA + c0aA - 2.0f*c0cA;                       \
                const float dyy0 = U0.x + L0.x - 2.0f*c0cA;                       \
                const float dyy1 = U0.y + L0.y - 2.0f*c1zA;                       \
                const float dxy0 = qn0A - q20A;                                   \
                const float dxy1 = qn1A - q21A;                                   \
                float s1 = dxx0 * dxx0;                                           \
                s1 = fmaf(dyy1, dyy1, s1);                                        \
                s1 = fmaf(dxy1, dxy1, s1);                                        \
                s1 = fmaf(dzz2A, dzz2A, s1);                                      \
                s1 = fmaf(dxz2A, dxz2A, s1);                                      \
                s1 = fmaf(dyz2A, dyz2A, s1);                                      \
                float s2 = dyy0 * dyy0;                                           \
                s2 = fmaf(dzz0A, dzz0A, s2);                                      \
                s2 = fmaf(dzz1A, dzz1A, s2);                                      \
                s2 = fmaf(dxz1A, dxz1A, s2);                                      \
                float s3 = dxy0 * dxy0;                                           \
                s3 = fmaf(dxz0A, dxz0A, s3);                                      \
                s3 = fmaf(dyz1A, dyz1A, s3);                                      \
                float t = fmaf(2.0f, s2, s1);                                     \
                t = fmaf(3.0f, s3, t);                                            \
                t = fmaf(4.0f * dyz0A, dyz0A, t);                                 \
                acc += t;                                                         \
            }                                                                     \
            {                                                                     \
                const float dxx0 = c0eB + c0aB - 2.0f*c0cB;                       \
                const float dyy0 = U1.y + L1.y - 2.0f*c0cB;                       \
                const float dyy1 = U2.x + L2.x - 2.0f*c1zB;                       \
                const float dxy0 = qn0B - q20B;                                   \
                const float dxy1 = qn1B - q21B;                                   \
                float s1 = dxx0 * dxx0;                                           \
                s1 = fmaf(dyy1, dyy1, s1);                                        \
                s1 = fmaf(dxy1, dxy1, s1);                                        \
                s1 = fmaf(dzz2B, dzz2B, s1);                                      \
                s1 = fmaf(dxz2B, dxz2B, s1);                                      \
                s1 = fmaf(dyz2B, dyz2B, s1);                                      \
                float s2 = dyy0 * dyy0;                                           \
                s2 = fmaf(dzz0B, dzz0B, s2);                                      \
                s2 = fmaf(dzz1B, dzz1B, s2);                                      \
                s2 = fmaf(dxz1B, dxz1B, s2);                                      \
                float s3 = dxy0 * dxy0;                                           \
                s3 = fmaf(dxz0B, dxz0B, s3);                                      \
                s3 = fmaf(dyz1B, dyz1B, s3);                                      \
                float t = fmaf(2.0f, s2, s1);                                     \
                t = fmaf(3.0f, s3, t);                                            \
                t = fmaf(4.0f * dyz0B, dyz0B, t);                                 \
                acc += t;                                                         \
            }                                                                     \
        }                                                                         \
        q20A = q10A; q21A = q11A; q20B = q10B; q21B = q11B;                       \
        q10A = qn0A; q11A = qn1A; q12A = qn2A;                                    \
        q10B = qn0B; q11B = qn1B; q12B = qn2B;                                    \
    }

    // 12 steps = 2 x 5 + 2; slot pattern period 5 (all literals)
    #pragma unroll 1
    for (int it = 0; it < 2; ++it) {
        DO_STEP(1, 2, 3, 4);
        DO_STEP(2, 3, 4, 0);
        DO_STEP(3, 4, 0, 1);
        DO_STEP(4, 0, 1, 2);
        DO_STEP(0, 1, 2, 3);
    }
    DO_STEP(1, 2, 3, 4);        // step 10
    DO_STEP(2, 3, 4, 0);        // step 11

    #undef DO_STEP

    // block reduction
    float v = acc;
    #pragma unroll
    for (int o = 16; o > 0; o >>= 1) v += __shfl_down_sync(0xffffffffu, v, o);
    if (tz == 0) warp_part[ty] = v;
    __syncthreads();
    if (tid == 0) {
        float s = 0.0f;
        #pragma unroll
        for (int w = 0; w < TY; ++w) s += warp_part[w];
        atomicAdd(&g_be_sum, (double)s);
        __threadfence();
        unsigned int t = atomicAdd(&g_be_cnt, 1u);
        if (t == NBLOCKS - 1) {
            double total = atomicAdd(&g_be_sum, 0.0);
            const double n = (double)BB * 156.0 * 156.0 * 156.0 * 3.0;
            out[0] = (float)(total / (16.0 * n));
            g_be_cnt = 0;
            g_be_sum = 0.0;
        }
    }
}

extern "C" void kernel_launch(void* const* d_in, const int* in_sizes, int n_in,
                              void* d_out, int out_size) {
    const float* grid = (const float*)d_in[0];
    float* out = (float*)d_out;

    static bool attr_set = false;
    if (!attr_set) {
        cudaFuncSetAttribute(be_main_kernel,
                             cudaFuncAttributeMaxDynamicSharedMemorySize,
                             5 * SLICE * (int)sizeof(float));
        attr_set = true;
    }

    dim3 blk(32, TY, 1);
    dim3 grd(NCHUNK, 13, BB * XSPLIT);
    be_main_kernel<<<grd, blk, 5 * SLICE * sizeof(float)>>>(grid, out);
}

// round 14
// speedup vs baseline: 1.3629x; 1.3629x over previous
#include <cuda_runtime.h>

// grid [2,160,160,160,3] float32
#define BB 2
#define NX 160
#define NY 160
#define NZ 160

#define TY 13                     // 12 y-tiles of 13 rows: kills the factor-13 grid
#define NCHUNK 6                  // z chunks, 28 outputs each (168 >= 156)
#define XSPLIT 6
#define XSTEPS 26                 // 156 / XSPLIT
#define NTHREADS (TY*32)          // 416
#define NBLOCKS (NCHUNK*12*BB*XSPLIT) // 864 = max 6 blocks/SM @ occ3: 2 exact rounds

#define RY (TY + 4)               // 17
#define RZ_ST 32                  // staged z per slice (z0-2 .. z0+29)
#define SLICE (RY * RZ_ST * 3)    // 1632 floats = 6528 B
#define ROWW (NZ * 3)             // 480 floats per (b,x,y) row
#define CPR (RZ_ST * 3 / 4)       // 24 16B chunks per staged row
#define CHUNKS (RY * CPR)         // 408 <= 416: one predicated cp16 per thread

__device__ double g_be_sum;
__device__ unsigned int g_be_cnt;

__device__ __forceinline__ void cp16(unsigned int dst_smem, const float* src) {
    asm volatile("cp.async.cg.shared.global [%0], [%1], 16;" :: "r"(dst_smem), "l"(src));
}
__device__ __forceinline__ void cp_commit() {
    asm volatile("cp.async.commit_group;" ::: "memory");
}
__device__ __forceinline__ void cp_wait0() {
    asm volatile("cp.async.wait_group 0;" ::: "memory");
}
__device__ __forceinline__ void cp_wait1() {
    asm volatile("cp.async.wait_group 1;" ::: "memory");
}

#define SHUP(v)  __shfl_up_sync(0xffffffffu, (v), 1)
#define SHDN(v)  __shfl_down_sync(0xffffffffu, (v), 1)
#define SHUP2(v) __shfl_up_sync(0xffffffffu, (v), 2)
#define SHDN2(v) __shfl_down_sync(0xffffffffu, (v), 2)

__global__ __launch_bounds__(NTHREADS, 3)
void be_main_kernel(const float* __restrict__ g, float* __restrict__ out) {
    __shared__ float ring[5 * SLICE];       // 32.6 KB static
    __shared__ float warp_part[TY];

    const int tz  = threadIdx.x;            // 0..31 (lane)
    const int ty  = threadIdx.y;            // 0..12
    const int tid = ty * 32 + tz;

    const int cz  = blockIdx.x;             // 0..5   z chunk (28 outputs each)
    const int cy  = blockIdx.y;             // 0..11  y tile (13 rows)
    const int b   = blockIdx.z / XSPLIT;
    const int seg = blockIdx.z % XSPLIT;

    const int z0 = 2 + cz * 28;             // first output z of this chunk
    const int y0 = 2 + cy * TY;
    const int xs = 2 + seg * XSTEPS;

    // lane l holds center z = z0 - 2 + l; outputs come from lanes 2..29
    const int zc = z0 - 2 + tz;
    const bool active = (tz >= 2) && (tz <= 29) && (zc <= NZ - 3);

    // ---- staging map: one predicated 16B chunk per thread (408 of 416) ----
    const int zbase3 = (z0 - 2) * 3;        // = 84*cz floats, 16B-aligned
    int goff;
    const bool stg = (tid < CHUNKS);
    {
        int t = stg ? tid : 0;
        int row = t / CPR, col = t - row * CPR;
        int o = zbase3 + col * 4;
        if (o > ROWW - 4) o = ROWW - 4;     // clamp: lands in unread lane-halo slack
        goff = row * ROWW + o;
    }

    const long long bbase = (long long)b * NX * NY * ROWW + (long long)(y0 - 2) * ROWW;
    const unsigned int ring_s = (unsigned int)__cvta_generic_to_shared(ring);

    auto issue_slice = [&](int gx, int slot) {
        const float* src = g + bbase + (long long)gx * (NY * ROWW);
        if (stg)
            cp16(ring_s + (unsigned int)(slot * SLICE) * 4u + (unsigned int)tid * 16u,
                 src + goff);
    };

    // ---- slot(x) = (x - xs + 2) mod 5; prologue: xs-2..xs+1 -> slots 0..3 ----
    issue_slice(xs - 2, 0);
    issue_slice(xs - 1, 1);
    issue_slice(xs,     2);
    issue_slice(xs + 1, 3);
    cp_commit();
    cp_wait0();
    __syncthreads();

    const int off0 = ((ty + 2) * RZ_ST + tz) * 3;
    #define Y (RZ_ST * 3)
    #define Zw 3

    // center delay lines: c0 x+2..x-2; c1,c2 x+2..x
    float c0a, c0b, c0c, c0d, c0e;
    float c1p2, c1p1, c1z, c2p2, c2p1, c2z;
    // q delay lines: q(s) = S_s[+off] - S_s[-off]
    float q2_xy0, q2_xy1, q2_xz0, q2_xz1, q2_xz2;
    float q1_xy0, q1_xy1, q1_xy2, q1_xz0, q1_xz1, q1_xz2;
    {
        const float* s;
        s = ring + 3 * SLICE; c0a = s[off0]; c1p2 = s[off0 + 1]; c2p2 = s[off0 + 2]; // xs+1
        s = ring + 2 * SLICE; c0b = s[off0]; c1p1 = s[off0 + 1]; c2p1 = s[off0 + 2]; // xs
        q1_xy0 = s[off0 + Y]      - s[off0 - Y];
        q1_xy1 = s[off0 + Y + 1]  - s[off0 - Y + 1];
        q1_xy2 = s[off0 + Y + 2]  - s[off0 - Y + 2];
        q1_xz0 = s[off0 + Zw]     - s[off0 - Zw];
        q1_xz1 = s[off0 + Zw + 1] - s[off0 - Zw + 1];
        q1_xz2 = s[off0 + Zw + 2] - s[off0 - Zw + 2];
        s = ring + 1 * SLICE; c0c = s[off0];                                          // xs-1
        q2_xy0 = s[off0 + Y]      - s[off0 - Y];
        q2_xy1 = s[off0 + Y + 1]  - s[off0 - Y + 1];
        q2_xz0 = s[off0 + Zw]     - s[off0 - Zw];
        q2_xz1 = s[off0 + Zw + 1] - s[off0 - Zw + 1];
        q2_xz2 = s[off0 + Zw + 2] - s[off0 - Zw + 2];
        s = ring;             c0d = s[off0];                                          // xs-2
        c0e = 0.f; c1z = 0.f; c2z = 0.f;
    }
    __syncthreads();            // init reads done before slot 0/4 reuse

    // pipeline: xs+2 -> slot 4, xs+3 -> slot 0 (two groups in flight)
    issue_slice(xs + 2, 4); cp_commit();
    issue_slice(xs + 3, 0); cp_commit();

    float acc = 0.0f;
    int gx4 = xs + 4;

    #define DO_STEP(SM1i, S0i, SP1i, SP2i)                                        \
    {                                                                             \
        cp_wait1();                                                               \
        __syncthreads();                                                          \
        {                                                                         \
            int gxs = gx4 > (NX - 1) ? (NX - 1) : gx4;                            \
            issue_slice(gxs, (SM1i)); cp_commit(); ++gx4;                         \
        }                                                                         \
        {                                                                         \
            const float* sp = ring + (SP2i) * SLICE;                              \
            float n0 = sp[off0], n1 = sp[off0 + 1], n2 = sp[off0 + 2];            \
            c0e = c0d; c0d = c0c; c0c = c0b; c0b = c0a; c0a = n0;                 \
            c1z = c1p1; c1p1 = c1p2; c1p2 = n1;                                   \
            c2z = c2p1; c2p1 = c2p2; c2p2 = n2;                                   \
        }                                                                         \
        const float* Sp1 = ring + (SP1i) * SLICE;                                 \
        const float qn_xy0 = Sp1[off0 + Y]     - Sp1[off0 - Y];                   \
        const float qn_xy1 = Sp1[off0 + Y + 1] - Sp1[off0 - Y + 1];               \
        const float qn_xy2 = Sp1[off0 + Y + 2] - Sp1[off0 - Y + 2];               \
        const float qn_xz0 = SHDN(c0b)  - SHUP(c0b);                              \
        const float qn_xz1 = SHDN(c1p1) - SHUP(c1p1);                             \
        const float qn_xz2 = SHDN(c2p1) - SHUP(c2p1);                             \
        const float dyz0 = SHDN(q1_xy0) - SHUP(q1_xy0);                           \
        const float dyz1 = SHDN(q1_xy1) - SHUP(q1_xy1);                           \
        const float dyz2 = SHDN(q1_xy2) - SHUP(q1_xy2);                           \
        const float dzz0 = SHUP2(c0c) + SHDN2(c0c) - 2.0f * c0c;                  \
        const float dzz1 = SHUP2(c1z) + SHDN2(c1z) - 2.0f * c1z;                  \
        const float dzz2 = SHUP2(c2z) + SHDN2(c2z) - 2.0f * c2z;                  \
        if (active) {                                                             \
            const float* S0 = ring + (S0i) * SLICE;                               \
            const float dxx0 = c0e + c0a - 2.0f * c0c;                            \
            const float dyy0 = S0[off0 - 2*Y]     + S0[off0 + 2*Y]     - 2.0f * c0c; \
            const float dyy1 = S0[off0 - 2*Y + 1] + S0[off0 + 2*Y + 1] - 2.0f * c1z; \
            const float dxy0 = qn_xy0 - q2_xy0;                                   \
            const float dxy1 = qn_xy1 - q2_xy1;                                   \
            const float dxz0 = qn_xz0 - q2_xz0;                                   \
            const float dxz1 = qn_xz1 - q2_xz1;                                   \
            const float dxz2 = qn_xz2 - q2_xz2;                                   \
            float s1 = dxx0 * dxx0;                                               \
            s1 = fmaf(dyy1, dyy1, s1);                                            \
            s1 = fmaf(dxy1, dxy1, s1);                                            \
            s1 = fmaf(dzz2, dzz2, s1);                                            \
            s1 = fmaf(dxz2, dxz2, s1);                                            \
            s1 = fmaf(dyz2, dyz2, s1);                                            \
            float s2 = dyy0 * dyy0;                                               \
            s2 = fmaf(dzz0, dzz0, s2);                                            \
            s2 = fmaf(dzz1, dzz1, s2);                                            \
            s2 = fmaf(dxz1, dxz1, s2);                                            \
            float s3 = dxy0 * dxy0;                                               \
            s3 = fmaf(dxz0, dxz0, s3);                                            \
            s3 = fmaf(dyz1, dyz1, s3);                                            \
            float t = fmaf(2.0f, s2, s1);                                         \
            t = fmaf(3.0f, s3, t);                                                \
            t = fmaf(4.0f * dyz0, dyz0, t);                                       \
            acc += t;                                                             \
        }                                                                         \
        q2_xy0 = q1_xy0; q2_xy1 = q1_xy1;                                         \
        q2_xz0 = q1_xz0; q2_xz1 = q1_xz1; q2_xz2 = q1_xz2;                        \
        q1_xy0 = qn_xy0; q1_xy1 = qn_xy1; q1_xy2 = qn_xy2;                        \
        q1_xz0 = qn_xz0; q1_xz1 = qn_xz1; q1_xz2 = qn_xz2;                        \
    }

    // 26 steps = 5 x 5 + 1 tail; slot pattern period 5 (all literals)
    #pragma unroll 1
    for (int it = 0; it < 5; ++it) {
        DO_STEP(1, 2, 3, 4);
        DO_STEP(2, 3, 4, 0);
        DO_STEP(3, 4, 0, 1);
        DO_STEP(4, 0, 1, 2);
        DO_STEP(0, 1, 2, 3);
    }
    DO_STEP(1, 2, 3, 4);        // step 25

    #undef DO_STEP
    #undef Y
    #undef Zw

    // block reduction
    float v = acc;
    #pragma unroll
    for (int o = 16; o > 0; o >>= 1) v += __shfl_down_sync(0xffffffffu, v, o);
    if (tz == 0) warp_part[ty] = v;
    __syncthreads();
    if (tid == 0) {
        float s = 0.0f;
        #pragma unroll
        for (int w = 0; w < TY; ++w) s += warp_part[w];
        atomicAdd(&g_be_sum, (double)s);
        __threadfence();
        unsigned int t = atomicAdd(&g_be_cnt, 1u);
        if (t == NBLOCKS - 1) {
            double total = atomicAdd(&g_be_sum, 0.0);   // ordered read of final sum
            const double n = (double)BB * 156.0 * 156.0 * 156.0 * 3.0;
            out[0] = (float)(total / (16.0 * n));
            g_be_cnt = 0;        // reset for next (graph-replayed) launch
            g_be_sum = 0.0;
        }
    }
}

extern "C" void kernel_launch(void* const* d_in, const int* in_sizes, int n_in,
                              void* d_out, int out_size) {
    const float* grid = (const float*)d_in[0];
    float* out = (float*)d_out;

    dim3 blk(32, TY, 1);
    dim3 grd(NCHUNK, 12, BB * XSPLIT);
    be_main_kernel<<<grd, blk>>>(grid, out);
}